// round 4
// baseline (speedup 1.0000x reference)
#include <cuda_runtime.h>
#include <cuda_bf16.h>
#include <cstdint>

// ---------------------------------------------------------------------------
// BoxMultiHeadedAttention  (B=16, N=256, D=512, H=8, d_k=64, dim_g=64)
//
//  K1 qkv_tf32       : q,k,v = (X @ W + b) -> [B,H,N,64]   (tf32 tensor-core)
//  K2 geo_bias_kernel: bias[b,h,n,m] = log(max(relu(geo.Wg+bg),1e-6)) (+mask)
//  K3 attn_fused     : O = softmax(bias + qk^T/8) @ V      (flash-style, tf32)
//  K4 outproj_tf32   : out = attn @ Wo + bo                (tf32 tensor-core)
// ---------------------------------------------------------------------------

#define Bz   16
#define Nn   256
#define Dm   512
#define Hh   8
#define DK   64

__device__ float g_q   [Bz*Hh*Nn*DK];
__device__ float g_k   [Bz*Hh*Nn*DK];
__device__ float g_v   [Bz*Hh*Nn*DK];
__device__ float g_bias[Bz*Hh*Nn*Nn];     // geo bias (read-only after K2)
__device__ float g_attn[Bz*Nn*Dm];

__device__ __forceinline__ float to_tf32(float x) {
    uint32_t u;
    asm("cvt.rna.tf32.f32 %0, %1;" : "=r"(u) : "f"(x));
    return __uint_as_float(u);
}
__device__ __forceinline__ uint32_t tf32u(float x) {
    uint32_t u;
    asm("cvt.rna.tf32.f32 %0, %1;" : "=r"(u) : "f"(x));
    return u;
}

__device__ __forceinline__ void mma_tf32(float c[4],
                                         uint32_t a0, uint32_t a1, uint32_t a2, uint32_t a3,
                                         uint32_t b0, uint32_t b1) {
    asm volatile(
        "mma.sync.aligned.m16n8k8.row.col.f32.tf32.tf32.f32 "
        "{%0,%1,%2,%3}, {%4,%5,%6,%7}, {%8,%9}, {%0,%1,%2,%3};\n"
        : "+f"(c[0]), "+f"(c[1]), "+f"(c[2]), "+f"(c[3])
        : "r"(a0), "r"(a1), "r"(a2), "r"(a3), "r"(b0), "r"(b1));
}

// ---------------------------------------------------------------------------
// tf32 tensor-core GEMM: C[M,512] = A[M,512] @ W[512,512] + bias
// Block tile 128x128, 8 warps, warp tile 32x64, k-chunk 32.
// ---------------------------------------------------------------------------
template <bool PERM>
__device__ __forceinline__ void gemm_tf32_body(const float* __restrict__ A,
                                               const float* __restrict__ W,
                                               const float* __restrict__ bias,
                                               float* __restrict__ C)
{
    __shared__ float As[128][36];
    __shared__ float Bs[32][136];

    const int t    = threadIdx.x;
    const int lane = t & 31;
    const int w    = t >> 5;
    const int g    = lane >> 2;
    const int tig  = lane & 3;
    const int wm   = w >> 1;
    const int wn   = w & 1;
    const int rowBase = blockIdx.y * 128;
    const int colBase = blockIdx.x * 128;

    const int ar = t >> 1, ak = (t & 1) * 16;
    const float* Ap = A + (size_t)(rowBase + ar) * Dm + ak;
    const int bk = t >> 3, bn = (t & 7) * 16;
    const float* Wp = W + (size_t)bk * Dm + colBase + bn;

    float acc[2][8][4];
#pragma unroll
    for (int mt = 0; mt < 2; ++mt)
#pragma unroll
        for (int nt = 0; nt < 8; ++nt)
#pragma unroll
            for (int i = 0; i < 4; ++i) acc[mt][nt][i] = 0.0f;

    for (int k0 = 0; k0 < Dm; k0 += 32) {
#pragma unroll
        for (int i = 0; i < 4; ++i) {
            float4 v = *(const float4*)(Ap + k0 + i * 4);
            v.x = to_tf32(v.x); v.y = to_tf32(v.y);
            v.z = to_tf32(v.z); v.w = to_tf32(v.w);
            *(float4*)&As[ar][ak + i * 4] = v;
        }
#pragma unroll
        for (int i = 0; i < 4; ++i) {
            float4 v = *(const float4*)(Wp + (size_t)k0 * Dm + i * 4);
            v.x = to_tf32(v.x); v.y = to_tf32(v.y);
            v.z = to_tf32(v.z); v.w = to_tf32(v.w);
            *(float4*)&Bs[bk][bn + i * 4] = v;
        }
        __syncthreads();

#pragma unroll
        for (int ks = 0; ks < 32; ks += 8) {
            uint32_t afr[2][4];
#pragma unroll
            for (int mt = 0; mt < 2; ++mt) {
                int mr = wm * 32 + mt * 16 + g;
                afr[mt][0] = __float_as_uint(As[mr    ][ks + tig    ]);
                afr[mt][1] = __float_as_uint(As[mr + 8][ks + tig    ]);
                afr[mt][2] = __float_as_uint(As[mr    ][ks + tig + 4]);
                afr[mt][3] = __float_as_uint(As[mr + 8][ks + tig + 4]);
            }
            uint32_t bfr[8][2];
#pragma unroll
            for (int nt = 0; nt < 8; ++nt) {
                int nc = wn * 64 + nt * 8 + g;
                bfr[nt][0] = __float_as_uint(Bs[ks + tig    ][nc]);
                bfr[nt][1] = __float_as_uint(Bs[ks + tig + 4][nc]);
            }
#pragma unroll
            for (int mt = 0; mt < 2; ++mt)
#pragma unroll
                for (int nt = 0; nt < 8; ++nt)
                    mma_tf32(acc[mt][nt],
                             afr[mt][0], afr[mt][1], afr[mt][2], afr[mt][3],
                             bfr[nt][0], bfr[nt][1]);
        }
        __syncthreads();
    }

#pragma unroll
    for (int mt = 0; mt < 2; ++mt) {
#pragma unroll
        for (int nt = 0; nt < 8; ++nt) {
            int r0 = rowBase + wm * 32 + mt * 16 + g;
            int c0 = colBase + wn * 64 + nt * 8 + 2 * tig;
            float v00 = acc[mt][nt][0] + bias[c0];
            float v01 = acc[mt][nt][1] + bias[c0 + 1];
            float v10 = acc[mt][nt][2] + bias[c0];
            float v11 = acc[mt][nt][3] + bias[c0 + 1];
            if (PERM) {
                int b_ = r0 >> 8, n_ = r0 & 255, h_ = c0 >> 6, d_ = c0 & 63;
                float* p0 = C + ((((b_ * Hh + h_) * Nn) + n_) * DK + d_);
                p0[0] = v00; p0[1] = v01;
                int r1 = r0 + 8;
                int b1_ = r1 >> 8, n1_ = r1 & 255;
                float* p1 = C + ((((b1_ * Hh + h_) * Nn) + n1_) * DK + d_);
                p1[0] = v10; p1[1] = v11;
            } else {
                *(float2*)(C + (size_t)r0 * Dm + c0)       = make_float2(v00, v01);
                *(float2*)(C + (size_t)(r0 + 8) * Dm + c0) = make_float2(v10, v11);
            }
        }
    }
}

__global__ __launch_bounds__(256, 2)
void qkv_tf32(const float* __restrict__ xq, const float* __restrict__ xk,
              const float* __restrict__ xv,
              const float* __restrict__ Wq, const float* __restrict__ bq,
              const float* __restrict__ Wk, const float* __restrict__ bk,
              const float* __restrict__ Wv, const float* __restrict__ bv)
{
    const float* A; const float* W; const float* bias; float* C;
    if (blockIdx.z == 0)      { A = xq; W = Wq; bias = bq; C = g_q; }
    else if (blockIdx.z == 1) { A = xk; W = Wk; bias = bk; C = g_k; }
    else                      { A = xv; W = Wv; bias = bv; C = g_v; }
    gemm_tf32_body<true>(A, W, bias, C);
}

__global__ __launch_bounds__(256, 2)
void outproj_tf32(const float* __restrict__ Wo, const float* __restrict__ bo,
                  float* __restrict__ out)
{
    gemm_tf32_body<false>(g_attn, Wo, bo, out);
}

// ---------------------------------------------------------------------------
// K2: geometric bias.  One block per (b,n), one thread per m.
// ---------------------------------------------------------------------------
__global__ void geo_bias_kernel(const float* __restrict__ box,
                                const int*   __restrict__ mask,
                                const float* __restrict__ WGw,
                                const float* __restrict__ WGb)
{
    __shared__ float Ws[8][32];
    __shared__ float Wc[8][32];
    __shared__ float Wb[8];

    const int t = threadIdx.x;
    const int n = blockIdx.x;
    const int b = blockIdx.y;

    for (int idx = t; idx < Hh * 64; idx += 256) {
        int h = idx >> 6, j = idx & 63;
        float w = WGw[idx];
        if (j < 32) Ws[h][j] = w; else Wc[h][j - 32] = w;
    }
    if (t < 8) Wb[t] = WGb[t];
    __syncthreads();

    float4 bn = *(const float4*)(box + (b * Nn + n) * 4);
    float4 bm = *(const float4*)(box + (b * Nn + t) * 4);
    float cx1 = (bn.x + bn.z) * 0.5f, cy1 = (bn.y + bn.w) * 0.5f;
    float w1  = bn.z - bn.x + 1.0f,   h1  = bn.w - bn.y + 1.0f;
    float cx2 = (bm.x + bm.z) * 0.5f, cy2 = (bm.y + bm.w) * 0.5f;
    float w2  = bm.z - bm.x + 1.0f,   h2  = bm.w - bm.y + 1.0f;

    float pos[4];
    pos[0] = logf(fmaxf(fabsf((cx1 - cx2) / w1), 0.001f));
    pos[1] = logf(fmaxf(fabsf((cy1 - cy2) / h1), 0.001f));
    pos[2] = logf(w1 / w2);
    pos[3] = logf(h1 / h2);

    const float dimv[8] = {1.0f, 0.42169650342f, 0.17782794100f, 0.07498942093f,
                           0.03162277660f, 0.01333521432f, 0.00562341325f,
                           0.00237137371f};

    float acc[8];
#pragma unroll
    for (int h = 0; h < 8; ++h) acc[h] = Wb[h];

#pragma unroll
    for (int p = 0; p < 4; ++p) {
        float base = 100.0f * pos[p];
#pragma unroll
        for (int f = 0; f < 8; ++f) {
            float s, c;
            sincosf(base * dimv[f], &s, &c);
            int j = p * 8 + f;
#pragma unroll
            for (int h = 0; h < 8; ++h) {
                acc[h] = fmaf(s, Ws[h][j], acc[h]);
                acc[h] = fmaf(c, Wc[h][j], acc[h]);
            }
        }
    }

    float mterm = (mask[b * Nn + t] == 0) ? -1e9f : 0.0f;
#pragma unroll
    for (int h = 0; h < 8; ++h) {
        float val = logf(fmaxf(acc[h], 1e-6f)) + mterm;
        g_bias[(((b * Hh + h) * Nn) + n) * Nn + t] = val;
    }
}

// ---------------------------------------------------------------------------
// K3: fused flash attention with additive bias.
// Block = 128 threads (4 warps) = 64 query rows of one (b,h).
// Each warp: 16 rows (m16). Keys processed in 4 chunks of 64, online softmax.
// QK^T and P@V both on tf32 mma. Bias read from g_bias; probs never stored.
// ---------------------------------------------------------------------------
__global__ __launch_bounds__(128)
void attn_fused_kernel()
{
    const int z = blockIdx.y;            // b*8+h
    const int b = z >> 3, h = z & 7;
    const int rowBase = blockIdx.x * 64;
    const float* Q  = g_q + (size_t)z * (Nn * DK);
    const float* Kg = g_k + (size_t)z * (Nn * DK);
    const float* Vg = g_v + (size_t)z * (Nn * DK);
    const float* Bias = g_bias + (size_t)z * (Nn * Nn);

    __shared__ float Ks[64][68];
    __shared__ float Vs[64][68];

    const int t    = threadIdx.x;
    const int lane = t & 31;
    const int w    = t >> 5;
    const int g    = lane >> 2;
    const int tig  = lane & 3;
    const int r0   = rowBase + w * 16 + g;     // rows r0 and r0+8

    // Q fragments, entire d=64 (8 k-chunks), resident in registers.
    uint32_t qf[8][4];
    {
        const float* Qr0 = Q + (size_t)r0 * DK;
        const float* Qr1 = Q + (size_t)(r0 + 8) * DK;
#pragma unroll
        for (int kc = 0; kc < 8; ++kc) {
            qf[kc][0] = tf32u(Qr0[kc * 8 + tig]);
            qf[kc][1] = tf32u(Qr1[kc * 8 + tig]);
            qf[kc][2] = tf32u(Qr0[kc * 8 + tig + 4]);
            qf[kc][3] = tf32u(Qr1[kc * 8 + tig + 4]);
        }
    }

    float o[8][4];
#pragma unroll
    for (int nt = 0; nt < 8; ++nt)
#pragma unroll
        for (int i = 0; i < 4; ++i) o[nt][i] = 0.0f;
    float m0 = -1e30f, m1 = -1e30f, l0 = 0.0f, l1 = 0.0f;

    const int kr  = t >> 1;              // 0..63
    const int kc4 = (t & 1) * 32;

    for (int key0 = 0; key0 < Nn; key0 += 64) {
        // stage K and V chunk (tf32-rounded)
#pragma unroll
        for (int i = 0; i < 8; ++i) {
            float4 kv = *(const float4*)(Kg + (size_t)(key0 + kr) * DK + kc4 + i * 4);
            kv.x = to_tf32(kv.x); kv.y = to_tf32(kv.y);
            kv.z = to_tf32(kv.z); kv.w = to_tf32(kv.w);
            *(float4*)&Ks[kr][kc4 + i * 4] = kv;
            float4 vv = *(const float4*)(Vg + (size_t)(key0 + kr) * DK + kc4 + i * 4);
            vv.x = to_tf32(vv.x); vv.y = to_tf32(vv.y);
            vv.z = to_tf32(vv.z); vv.w = to_tf32(vv.w);
            *(float4*)&Vs[kr][kc4 + i * 4] = vv;
        }
        __syncthreads();

        // S = Q K^T for this 64-key chunk: 8 n-tiles of 8 keys
        float s[8][4];
#pragma unroll
        for (int nt = 0; nt < 8; ++nt) {
            s[nt][0] = s[nt][1] = s[nt][2] = s[nt][3] = 0.0f;
#pragma unroll
            for (int kc = 0; kc < 8; ++kc) {
                uint32_t b0 = __float_as_uint(Ks[nt * 8 + g][kc * 8 + tig]);
                uint32_t b1 = __float_as_uint(Ks[nt * 8 + g][kc * 8 + tig + 4]);
                mma_tf32(s[nt], qf[kc][0], qf[kc][1], qf[kc][2], qf[kc][3], b0, b1);
            }
        }

        // scale + bias
#pragma unroll
        for (int nt = 0; nt < 8; ++nt) {
            int col = key0 + nt * 8 + 2 * tig;
            float2 bv0 = *(const float2*)(Bias + (size_t)r0 * Nn + col);
            float2 bv1 = *(const float2*)(Bias + (size_t)(r0 + 8) * Nn + col);
            s[nt][0] = fmaf(s[nt][0], 0.125f, bv0.x);
            s[nt][1] = fmaf(s[nt][1], 0.125f, bv0.y);
            s[nt][2] = fmaf(s[nt][2], 0.125f, bv1.x);
            s[nt][3] = fmaf(s[nt][3], 0.125f, bv1.y);
        }

        // chunk row max (reduce across the 4 quad lanes)
        float cm0 = -1e30f, cm1 = -1e30f;
#pragma unroll
        for (int nt = 0; nt < 8; ++nt) {
            cm0 = fmaxf(cm0, fmaxf(s[nt][0], s[nt][1]));
            cm1 = fmaxf(cm1, fmaxf(s[nt][2], s[nt][3]));
        }
        cm0 = fmaxf(cm0, __shfl_xor_sync(0xffffffffu, cm0, 1));
        cm0 = fmaxf(cm0, __shfl_xor_sync(0xffffffffu, cm0, 2));
        cm1 = fmaxf(cm1, __shfl_xor_sync(0xffffffffu, cm1, 1));
        cm1 = fmaxf(cm1, __shfl_xor_sync(0xffffffffu, cm1, 2));

        float m0n = fmaxf(m0, cm0);
        float m1n = fmaxf(m1, cm1);
        float sc0 = __expf(m0 - m0n);
        float sc1 = __expf(m1 - m1n);
        m0 = m0n; m1 = m1n;

        // P = exp(S - m), chunk sums
        float cs0 = 0.0f, cs1 = 0.0f;
#pragma unroll
        for (int nt = 0; nt < 8; ++nt) {
            s[nt][0] = __expf(s[nt][0] - m0n);
            s[nt][1] = __expf(s[nt][1] - m0n);
            s[nt][2] = __expf(s[nt][2] - m1n);
            s[nt][3] = __expf(s[nt][3] - m1n);
            cs0 += s[nt][0] + s[nt][1];
            cs1 += s[nt][2] + s[nt][3];
        }
        cs0 += __shfl_xor_sync(0xffffffffu, cs0, 1);
        cs0 += __shfl_xor_sync(0xffffffffu, cs0, 2);
        cs1 += __shfl_xor_sync(0xffffffffu, cs1, 1);
        cs1 += __shfl_xor_sync(0xffffffffu, cs1, 2);
        l0 = l0 * sc0 + cs0;
        l1 = l1 * sc1 + cs1;

        // rescale accumulated output
#pragma unroll
        for (int nt = 0; nt < 8; ++nt) {
            o[nt][0] *= sc0; o[nt][1] *= sc0;
            o[nt][2] *= sc1; o[nt][3] *= sc1;
        }

        // O += P @ V  (C-frag -> A-frag via quad shuffles)
        const int base = lane & ~3;
#pragma unroll
        for (int kc = 0; kc < 8; ++kc) {
            int s0l = base + (tig >> 1);
            int s1l = s0l + 2;
            float x0 = __shfl_sync(0xffffffffu, s[kc][0], s0l);
            float x1 = __shfl_sync(0xffffffffu, s[kc][1], s0l);
            float x2 = __shfl_sync(0xffffffffu, s[kc][2], s0l);
            float x3 = __shfl_sync(0xffffffffu, s[kc][3], s0l);
            float y0 = __shfl_sync(0xffffffffu, s[kc][0], s1l);
            float y1 = __shfl_sync(0xffffffffu, s[kc][1], s1l);
            float y2 = __shfl_sync(0xffffffffu, s[kc][2], s1l);
            float y3 = __shfl_sync(0xffffffffu, s[kc][3], s1l);
            bool odd = (tig & 1);
            uint32_t a0 = tf32u(odd ? x1 : x0);
            uint32_t a1 = tf32u(odd ? x3 : x2);
            uint32_t a2 = tf32u(odd ? y1 : y0);
            uint32_t a3 = tf32u(odd ? y3 : y2);
#pragma unroll
            for (int nt = 0; nt < 8; ++nt) {
                uint32_t b0 = __float_as_uint(Vs[kc * 8 + tig    ][nt * 8 + g]);
                uint32_t b1 = __float_as_uint(Vs[kc * 8 + tig + 4][nt * 8 + g]);
                mma_tf32(o[nt], a0, a1, a2, a3, b0, b1);
            }
        }
        __syncthreads();
    }

    // normalize and write [B, N, H*64]
    float inv0 = 1.0f / l0;
    float inv1 = 1.0f / l1;
#pragma unroll
    for (int nt = 0; nt < 8; ++nt) {
        int d = nt * 8 + 2 * tig;
        float* p0 = g_attn + ((size_t)(b * Nn + r0) * Dm + h * DK + d);
        float* p1 = g_attn + ((size_t)(b * Nn + r0 + 8) * Dm + h * DK + d);
        *(float2*)p0 = make_float2(o[nt][0] * inv0, o[nt][1] * inv0);
        *(float2*)p1 = make_float2(o[nt][2] * inv1, o[nt][3] * inv1);
    }
}

// ---------------------------------------------------------------------------
extern "C" void kernel_launch(void* const* d_in, const int* in_sizes, int n_in,
                              void* d_out, int out_size)
{
    const float* xq  = (const float*)d_in[0];
    const float* xk  = (const float*)d_in[1];
    const float* xv  = (const float*)d_in[2];
    const float* box = (const float*)d_in[3];
    const int*   msk = (const int*)  d_in[4];
    const float* Wq  = (const float*)d_in[5];
    const float* bq  = (const float*)d_in[6];
    const float* Wk  = (const float*)d_in[7];
    const float* bk  = (const float*)d_in[8];
    const float* Wv  = (const float*)d_in[9];
    const float* bv  = (const float*)d_in[10];
    const float* Wo  = (const float*)d_in[11];
    const float* bo  = (const float*)d_in[12];
    const float* WGw = (const float*)d_in[13];
    const float* WGb = (const float*)d_in[14];
    float* out = (float*)d_out;

    qkv_tf32<<<dim3(4, 32, 3), 256>>>(xq, xk, xv, Wq, bq, Wk, bk, Wv, bv);
    geo_bias_kernel<<<dim3(Nn, Bz), 256>>>(box, msk, WGw, WGb);
    attn_fused_kernel<<<dim3(4, Bz * Hh), 128>>>();
    outproj_tf32<<<dim3(4, 32, 1), 256>>>(Wo, bo, out);
}

// round 5
// speedup vs baseline: 1.2152x; 1.2152x over previous
#include <cuda_runtime.h>
#include <cuda_bf16.h>
#include <cstdint>

// ---------------------------------------------------------------------------
// BoxMultiHeadedAttention  (B=16, N=256, D=512, H=8, d_k=64, dim_g=64)
//
//  K1 qkv_tf32      : q,k,v = (X @ W + b) -> [B,H,N,64]   (tf32 mma, 64x64 DB)
//  K2 geo_bias      : bias[b,h,n,m] = log(max(relu(geo.Wg+bg),1e-6)) (+mask)
//  K3 scores_mma    : g_bias = bias + qk^T/8   (tf32 mma, in place)
//  K4 softmax_fast  : row softmax in place (warp per row, float4)
//  K5 pv_mma        : attn = P @ V  (tf32 mma)
//  K6 outproj_tf32  : out = attn @ Wo + bo
// ---------------------------------------------------------------------------

#define Bz   16
#define Nn   256
#define Dm   512
#define Hh   8
#define DK   64

__device__ float g_q   [Bz*Hh*Nn*DK];
__device__ float g_k   [Bz*Hh*Nn*DK];
__device__ float g_v   [Bz*Hh*Nn*DK];
__device__ float g_bias[Bz*Hh*Nn*Nn];     // bias -> logits -> probs (in place)
__device__ float g_attn[Bz*Nn*Dm];

__device__ __forceinline__ float to_tf32(float x) {
    uint32_t u;
    asm("cvt.rna.tf32.f32 %0, %1;" : "=r"(u) : "f"(x));
    return __uint_as_float(u);
}

__device__ __forceinline__ void mma_tf32(float c[4],
                                         uint32_t a0, uint32_t a1, uint32_t a2, uint32_t a3,
                                         uint32_t b0, uint32_t b1) {
    asm volatile(
        "mma.sync.aligned.m16n8k8.row.col.f32.tf32.tf32.f32 "
        "{%0,%1,%2,%3}, {%4,%5,%6,%7}, {%8,%9}, {%0,%1,%2,%3};\n"
        : "+f"(c[0]), "+f"(c[1]), "+f"(c[2]), "+f"(c[3])
        : "r"(a0), "r"(a1), "r"(a2), "r"(a3), "r"(b0), "r"(b1));
}

__device__ __forceinline__ float4 tf32_4(float4 v) {
    v.x = to_tf32(v.x); v.y = to_tf32(v.y);
    v.z = to_tf32(v.z); v.w = to_tf32(v.w);
    return v;
}

// ---------------------------------------------------------------------------
// tf32 GEMM: C[M,512] = A[M,512] @ W[512,512] + bias
// Block tile 64x64, k-chunk 32, double-buffered smem, 128 threads (4 warps),
// warp tile 32x32.
// ---------------------------------------------------------------------------
template <bool PERM>
__device__ __forceinline__ void gemm_tf32_body(const float* __restrict__ A,
                                               const float* __restrict__ W,
                                               const float* __restrict__ bias,
                                               float* __restrict__ C)
{
    __shared__ float As[2][64][36];   // [buf][m][k]
    __shared__ float Bs[2][32][72];   // [buf][k][n]

    const int t    = threadIdx.x;
    const int lane = t & 31;
    const int w    = t >> 5;
    const int g    = lane >> 2;
    const int tig  = lane & 3;
    const int wm   = w >> 1;          // 0..1
    const int wn   = w & 1;           // 0..1
    const int rowBase = blockIdx.y * 64;
    const int colBase = blockIdx.x * 64;

    const int ar = t >> 1,  ak = (t & 1) * 16;   // A: 64 rows x 32 k
    const int bk = t >> 2,  bn = (t & 3) * 16;   // B: 32 k x 64 n
    const float* Ap = A + (size_t)(rowBase + ar) * Dm + ak;
    const float* Wp = W + (size_t)bk * Dm + colBase + bn;

    float acc[2][4][4];
#pragma unroll
    for (int mt = 0; mt < 2; ++mt)
#pragma unroll
        for (int nt = 0; nt < 4; ++nt)
#pragma unroll
            for (int i = 0; i < 4; ++i) acc[mt][nt][i] = 0.0f;

    // prologue: chunk 0 -> buf 0
#pragma unroll
    for (int i = 0; i < 4; ++i)
        *(float4*)&As[0][ar][ak + i * 4] = tf32_4(*(const float4*)(Ap + i * 4));
#pragma unroll
    for (int i = 0; i < 4; ++i)
        *(float4*)&Bs[0][bk][bn + i * 4] = tf32_4(*(const float4*)(Wp + i * 4));
    __syncthreads();

    const int NK = Dm / 32;          // 16
    for (int it = 0; it < NK; ++it) {
        float4 pa[4], pb[4];
        const bool more = (it + 1 < NK);
        if (more) {
            const int k0 = (it + 1) * 32;
#pragma unroll
            for (int i = 0; i < 4; ++i) pa[i] = *(const float4*)(Ap + k0 + i * 4);
#pragma unroll
            for (int i = 0; i < 4; ++i) pb[i] = *(const float4*)(Wp + (size_t)k0 * Dm + i * 4);
        }

        const int buf = it & 1;
#pragma unroll
        for (int ks = 0; ks < 32; ks += 8) {
            uint32_t afr[2][4];
#pragma unroll
            for (int mt = 0; mt < 2; ++mt) {
                int mr = wm * 32 + mt * 16 + g;
                afr[mt][0] = __float_as_uint(As[buf][mr    ][ks + tig    ]);
                afr[mt][1] = __float_as_uint(As[buf][mr + 8][ks + tig    ]);
                afr[mt][2] = __float_as_uint(As[buf][mr    ][ks + tig + 4]);
                afr[mt][3] = __float_as_uint(As[buf][mr + 8][ks + tig + 4]);
            }
            uint32_t bfr[4][2];
#pragma unroll
            for (int nt = 0; nt < 4; ++nt) {
                int nc = wn * 32 + nt * 8 + g;
                bfr[nt][0] = __float_as_uint(Bs[buf][ks + tig    ][nc]);
                bfr[nt][1] = __float_as_uint(Bs[buf][ks + tig + 4][nc]);
            }
#pragma unroll
            for (int mt = 0; mt < 2; ++mt)
#pragma unroll
                for (int nt = 0; nt < 4; ++nt)
                    mma_tf32(acc[mt][nt],
                             afr[mt][0], afr[mt][1], afr[mt][2], afr[mt][3],
                             bfr[nt][0], bfr[nt][1]);
        }

        if (more) {
            const int nb = 1 - buf;
#pragma unroll
            for (int i = 0; i < 4; ++i) *(float4*)&As[nb][ar][ak + i * 4] = tf32_4(pa[i]);
#pragma unroll
            for (int i = 0; i < 4; ++i) *(float4*)&Bs[nb][bk][bn + i * 4] = tf32_4(pb[i]);
        }
        __syncthreads();
    }

#pragma unroll
    for (int mt = 0; mt < 2; ++mt) {
#pragma unroll
        for (int nt = 0; nt < 4; ++nt) {
            int r0 = rowBase + wm * 32 + mt * 16 + g;
            int c0 = colBase + wn * 32 + nt * 8 + 2 * tig;
            float v00 = acc[mt][nt][0] + bias[c0];
            float v01 = acc[mt][nt][1] + bias[c0 + 1];
            float v10 = acc[mt][nt][2] + bias[c0];
            float v11 = acc[mt][nt][3] + bias[c0 + 1];
            if (PERM) {
                int b_ = r0 >> 8, n_ = r0 & 255, h_ = c0 >> 6, d_ = c0 & 63;
                float* p0 = C + ((((b_ * Hh + h_) * Nn) + n_) * DK + d_);
                p0[0] = v00; p0[1] = v01;
                int r1 = r0 + 8;
                int b1_ = r1 >> 8, n1_ = r1 & 255;
                float* p1 = C + ((((b1_ * Hh + h_) * Nn) + n1_) * DK + d_);
                p1[0] = v10; p1[1] = v11;
            } else {
                *(float2*)(C + (size_t)r0 * Dm + c0)       = make_float2(v00, v01);
                *(float2*)(C + (size_t)(r0 + 8) * Dm + c0) = make_float2(v10, v11);
            }
        }
    }
}

__global__ __launch_bounds__(128)
void qkv_tf32(const float* __restrict__ xq, const float* __restrict__ xk,
              const float* __restrict__ xv,
              const float* __restrict__ Wq, const float* __restrict__ bq,
              const float* __restrict__ Wk, const float* __restrict__ bk,
              const float* __restrict__ Wv, const float* __restrict__ bv)
{
    const float* A; const float* W; const float* bias; float* C;
    if (blockIdx.z == 0)      { A = xq; W = Wq; bias = bq; C = g_q; }
    else if (blockIdx.z == 1) { A = xk; W = Wk; bias = bk; C = g_k; }
    else                      { A = xv; W = Wv; bias = bv; C = g_v; }
    gemm_tf32_body<true>(A, W, bias, C);
}

__global__ __launch_bounds__(128)
void outproj_tf32(const float* __restrict__ Wo, const float* __restrict__ bo,
                  float* __restrict__ out)
{
    gemm_tf32_body<false>(g_attn, Wo, bo, out);
}

// ---------------------------------------------------------------------------
// K2: geometric bias.  One block per (b,n), one thread per m.
// ---------------------------------------------------------------------------
__global__ void geo_bias_kernel(const float* __restrict__ box,
                                const int*   __restrict__ mask,
                                const float* __restrict__ WGw,
                                const float* __restrict__ WGb)
{
    __shared__ float Ws[8][32];
    __shared__ float Wc[8][32];
    __shared__ float Wb[8];

    const int t = threadIdx.x;
    const int n = blockIdx.x;
    const int b = blockIdx.y;

    for (int idx = t; idx < Hh * 64; idx += 256) {
        int h = idx >> 6, j = idx & 63;
        float w = WGw[idx];
        if (j < 32) Ws[h][j] = w; else Wc[h][j - 32] = w;
    }
    if (t < 8) Wb[t] = WGb[t];
    __syncthreads();

    float4 bn = *(const float4*)(box + (b * Nn + n) * 4);
    float4 bm = *(const float4*)(box + (b * Nn + t) * 4);
    float cx1 = (bn.x + bn.z) * 0.5f, cy1 = (bn.y + bn.w) * 0.5f;
    float w1  = bn.z - bn.x + 1.0f,   h1  = bn.w - bn.y + 1.0f;
    float cx2 = (bm.x + bm.z) * 0.5f, cy2 = (bm.y + bm.w) * 0.5f;
    float w2  = bm.z - bm.x + 1.0f,   h2  = bm.w - bm.y + 1.0f;

    float pos[4];
    pos[0] = logf(fmaxf(fabsf((cx1 - cx2) / w1), 0.001f));
    pos[1] = logf(fmaxf(fabsf((cy1 - cy2) / h1), 0.001f));
    pos[2] = logf(w1 / w2);
    pos[3] = logf(h1 / h2);

    const float dimv[8] = {1.0f, 0.42169650342f, 0.17782794100f, 0.07498942093f,
                           0.03162277660f, 0.01333521432f, 0.00562341325f,
                           0.00237137371f};

    float acc[8];
#pragma unroll
    for (int h = 0; h < 8; ++h) acc[h] = Wb[h];

#pragma unroll
    for (int p = 0; p < 4; ++p) {
        float base = 100.0f * pos[p];
#pragma unroll
        for (int f = 0; f < 8; ++f) {
            float s, c;
            sincosf(base * dimv[f], &s, &c);
            int j = p * 8 + f;
#pragma unroll
            for (int h = 0; h < 8; ++h) {
                acc[h] = fmaf(s, Ws[h][j], acc[h]);
                acc[h] = fmaf(c, Wc[h][j], acc[h]);
            }
        }
    }

    float mterm = (mask[b * Nn + t] == 0) ? -1e9f : 0.0f;
#pragma unroll
    for (int h = 0; h < 8; ++h) {
        float val = logf(fmaxf(acc[h], 1e-6f)) + mterm;
        g_bias[(((b * Hh + h) * Nn) + n) * Nn + t] = val;
    }
}

// ---------------------------------------------------------------------------
// K3: logits = bias + qk^T/8, tf32 mma, in place over g_bias.
// Block: 64 q-rows x 64 keys of one (b,h); d_k=64 staged once (no k-loop).
// ---------------------------------------------------------------------------
__global__ __launch_bounds__(128)
void scores_mma_kernel()
{
    const int z = blockIdx.z;                 // b*8+h
    const float* Q  = g_q + (size_t)z * (Nn * DK);
    const float* Kg = g_k + (size_t)z * (Nn * DK);
    float* S = g_bias + (size_t)z * (Nn * Nn);

    __shared__ float Qs[64][68];   // [m][d]
    __shared__ float Ks[64][68];   // [key][d]

    const int t    = threadIdx.x;
    const int lane = t & 31;
    const int w    = t >> 5;
    const int g    = lane >> 2;
    const int tig  = lane & 3;
    const int wm   = w >> 1;
    const int wn   = w & 1;
    const int rowBase = blockIdx.y * 64;
    const int colBase = blockIdx.x * 64;

    // stage Q and K tiles: 64x64 each; 128 threads * 8 float4 each
    const int sr = t >> 1, sc = (t & 1) * 32;
#pragma unroll
    for (int i = 0; i < 8; ++i) {
        *(float4*)&Qs[sr][sc + i * 4] =
            tf32_4(*(const float4*)(Q + (size_t)(rowBase + sr) * DK + sc + i * 4));
        *(float4*)&Ks[sr][sc + i * 4] =
            tf32_4(*(const float4*)(Kg + (size_t)(colBase + sr) * DK + sc + i * 4));
    }
    __syncthreads();

    float acc[2][4][4];
#pragma unroll
    for (int mt = 0; mt < 2; ++mt)
#pragma unroll
        for (int nt = 0; nt < 4; ++nt)
#pragma unroll
            for (int i = 0; i < 4; ++i) acc[mt][nt][i] = 0.0f;

#pragma unroll
    for (int ks = 0; ks < 64; ks += 8) {
        uint32_t afr[2][4];
#pragma unroll
        for (int mt = 0; mt < 2; ++mt) {
            int mr = wm * 32 + mt * 16 + g;
            afr[mt][0] = __float_as_uint(Qs[mr    ][ks + tig    ]);
            afr[mt][1] = __float_as_uint(Qs[mr + 8][ks + tig    ]);
            afr[mt][2] = __float_as_uint(Qs[mr    ][ks + tig + 4]);
            afr[mt][3] = __float_as_uint(Qs[mr + 8][ks + tig + 4]);
        }
        uint32_t bfr[4][2];
#pragma unroll
        for (int nt = 0; nt < 4; ++nt) {
            int nc = wn * 32 + nt * 8 + g;               // key index
            bfr[nt][0] = __float_as_uint(Ks[nc][ks + tig    ]);
            bfr[nt][1] = __float_as_uint(Ks[nc][ks + tig + 4]);
        }
#pragma unroll
        for (int mt = 0; mt < 2; ++mt)
#pragma unroll
            for (int nt = 0; nt < 4; ++nt)
                mma_tf32(acc[mt][nt],
                         afr[mt][0], afr[mt][1], afr[mt][2], afr[mt][3],
                         bfr[nt][0], bfr[nt][1]);
    }

#pragma unroll
    for (int mt = 0; mt < 2; ++mt)
#pragma unroll
        for (int nt = 0; nt < 4; ++nt) {
            int r0 = rowBase + wm * 32 + mt * 16 + g;
            int c0 = colBase + wn * 32 + nt * 8 + 2 * tig;
            float* p0 = S + (size_t)r0 * Nn + c0;
            float* p1 = S + (size_t)(r0 + 8) * Nn + c0;
            p0[0] = fmaf(acc[mt][nt][0], 0.125f, p0[0]);
            p0[1] = fmaf(acc[mt][nt][1], 0.125f, p0[1]);
            p1[0] = fmaf(acc[mt][nt][2], 0.125f, p1[0]);
            p1[1] = fmaf(acc[mt][nt][3], 0.125f, p1[1]);
        }
}

// ---------------------------------------------------------------------------
// K4: softmax, one warp per row (256 cols, 8 per lane), in place.
// ---------------------------------------------------------------------------
__global__ __launch_bounds__(256)
void softmax_fast_kernel()
{
    const int row  = blockIdx.x * 8 + (threadIdx.x >> 5);
    const int lane = threadIdx.x & 31;
    float* p = g_bias + (size_t)row * Nn + lane * 8;

    float4 v0 = *(const float4*)p;
    float4 v1 = *(const float4*)(p + 4);

    float m = fmaxf(fmaxf(fmaxf(v0.x, v0.y), fmaxf(v0.z, v0.w)),
                    fmaxf(fmaxf(v1.x, v1.y), fmaxf(v1.z, v1.w)));
#pragma unroll
    for (int o = 16; o > 0; o >>= 1)
        m = fmaxf(m, __shfl_xor_sync(0xffffffffu, m, o));

    v0.x = __expf(v0.x - m); v0.y = __expf(v0.y - m);
    v0.z = __expf(v0.z - m); v0.w = __expf(v0.w - m);
    v1.x = __expf(v1.x - m); v1.y = __expf(v1.y - m);
    v1.z = __expf(v1.z - m); v1.w = __expf(v1.w - m);

    float s = v0.x + v0.y + v0.z + v0.w + v1.x + v1.y + v1.z + v1.w;
#pragma unroll
    for (int o = 16; o > 0; o >>= 1)
        s += __shfl_xor_sync(0xffffffffu, s, o);

    float inv = __frcp_rn(s);
    v0.x *= inv; v0.y *= inv; v0.z *= inv; v0.w *= inv;
    v1.x *= inv; v1.y *= inv; v1.z *= inv; v1.w *= inv;
    *(float4*)p       = v0;
    *(float4*)(p + 4) = v1;
}

// ---------------------------------------------------------------------------
// K5: attn = P @ V, tf32 mma.  Block: 64 rows x 64 dims, k-loop 4x64 keys.
// ---------------------------------------------------------------------------
__global__ __launch_bounds__(128)
void pv_mma_kernel()
{
    const int z = blockIdx.z;                 // b*8+h
    const int b = z >> 3, h = z & 7;
    const float* P = g_bias + (size_t)z * (Nn * Nn);
    const float* V = g_v + (size_t)z * (Nn * DK);
    const int rowBase = blockIdx.y * 64;

    __shared__ float Ps[64][68];   // [row][key]
    __shared__ float Vs[64][68];   // [key][dim]

    const int t    = threadIdx.x;
    const int lane = t & 31;
    const int w    = t >> 5;
    const int g    = lane >> 2;
    const int tig  = lane & 3;
    const int wm   = w >> 1;
    const int wn   = w & 1;

    float acc[2][4][4];
#pragma unroll
    for (int mt = 0; mt < 2; ++mt)
#pragma unroll
        for (int nt = 0; nt < 4; ++nt)
#pragma unroll
            for (int i = 0; i < 4; ++i) acc[mt][nt][i] = 0.0f;

    const int sr = t >> 1, sc = (t & 1) * 32;

    for (int key0 = 0; key0 < Nn; key0 += 64) {
#pragma unroll
        for (int i = 0; i < 8; ++i) {
            *(float4*)&Ps[sr][sc + i * 4] =
                tf32_4(*(const float4*)(P + (size_t)(rowBase + sr) * Nn + key0 + sc + i * 4));
            *(float4*)&Vs[sr][sc + i * 4] =
                tf32_4(*(const float4*)(V + (size_t)(key0 + sr) * DK + sc + i * 4));
        }
        __syncthreads();

#pragma unroll
        for (int ks = 0; ks < 64; ks += 8) {
            uint32_t afr[2][4];
#pragma unroll
            for (int mt = 0; mt < 2; ++mt) {
                int mr = wm * 32 + mt * 16 + g;
                afr[mt][0] = __float_as_uint(Ps[mr    ][ks + tig    ]);
                afr[mt][1] = __float_as_uint(Ps[mr + 8][ks + tig    ]);
                afr[mt][2] = __float_as_uint(Ps[mr    ][ks + tig + 4]);
                afr[mt][3] = __float_as_uint(Ps[mr + 8][ks + tig + 4]);
            }
            uint32_t bfr[4][2];
#pragma unroll
            for (int nt = 0; nt < 4; ++nt) {
                int nc = wn * 32 + nt * 8 + g;           // dim
                bfr[nt][0] = __float_as_uint(Vs[ks + tig    ][nc]);
                bfr[nt][1] = __float_as_uint(Vs[ks + tig + 4][nc]);
            }
#pragma unroll
            for (int mt = 0; mt < 2; ++mt)
#pragma unroll
                for (int nt = 0; nt < 4; ++nt)
                    mma_tf32(acc[mt][nt],
                             afr[mt][0], afr[mt][1], afr[mt][2], afr[mt][3],
                             bfr[nt][0], bfr[nt][1]);
        }
        __syncthreads();
    }

#pragma unroll
    for (int mt = 0; mt < 2; ++mt)
#pragma unroll
        for (int nt = 0; nt < 4; ++nt) {
            int r0 = rowBase + wm * 32 + mt * 16 + g;
            int c0 = wn * 32 + nt * 8 + 2 * tig;
            float* p0 = g_attn + ((size_t)(b * Nn + r0) * Dm + h * DK + c0);
            float* p1 = g_attn + ((size_t)(b * Nn + r0 + 8) * Dm + h * DK + c0);
            *(float2*)p0 = make_float2(acc[mt][nt][0], acc[mt][nt][1]);
            *(float2*)p1 = make_float2(acc[mt][nt][2], acc[mt][nt][3]);
        }
}

// ---------------------------------------------------------------------------
extern "C" void kernel_launch(void* const* d_in, const int* in_sizes, int n_in,
                              void* d_out, int out_size)
{
    const float* xq  = (const float*)d_in[0];
    const float* xk  = (const float*)d_in[1];
    const float* xv  = (const float*)d_in[2];
    const float* box = (const float*)d_in[3];
    const int*   msk = (const int*)  d_in[4];
    const float* Wq  = (const float*)d_in[5];
    const float* bq  = (const float*)d_in[6];
    const float* Wk  = (const float*)d_in[7];
    const float* bk  = (const float*)d_in[8];
    const float* Wv  = (const float*)d_in[9];
    const float* bv  = (const float*)d_in[10];
    const float* Wo  = (const float*)d_in[11];
    const float* bo  = (const float*)d_in[12];
    const float* WGw = (const float*)d_in[13];
    const float* WGb = (const float*)d_in[14];
    float* out = (float*)d_out;

    qkv_tf32<<<dim3(8, 64, 3), 128>>>(xq, xk, xv, Wq, bq, Wk, bk, Wv, bv);
    geo_bias_kernel<<<dim3(Nn, Bz), 256>>>(box, msk, WGw, WGb);
    scores_mma_kernel<<<dim3(4, 4, Bz * Hh), 128>>>();
    softmax_fast_kernel<<<Bz * Hh * Nn / 8, 256>>>();
    pv_mma_kernel<<<dim3(1, 4, Bz * Hh), 128>>>();
    outproj_tf32<<<dim3(8, 64, 1), 128>>>(Wo, bo, out);
}

// round 7
// speedup vs baseline: 1.3835x; 1.1385x over previous
#include <cuda_runtime.h>
#include <cuda_bf16.h>
#include <cstdint>

// ---------------------------------------------------------------------------
// BoxMultiHeadedAttention  (B=16, N=256, D=512, H=8, d_k=64, dim_g=64)
//
//  K1 qkv_tf32   : q,k,v = (X @ W + b) -> [B,H,N,64]   (tf32 mma, 64x64 DB)
//  K2 geo_bias   : bias[b,h,n,m] = log(max(relu(geo.Wg+bg),1e-6)) (+mask)
//  K3 attn_core  : O = softmax(bias + qk^T/8) @ V  (fused: S-mma, exact
//                  softmax in regs, P via smem, PV-mma). bias read once.
//  K4 outproj    : out = attn @ Wo + bo
// ---------------------------------------------------------------------------

#define Bz   16
#define Nn   256
#define Dm   512
#define Hh   8
#define DK   64

__device__ float g_q   [Bz*Hh*Nn*DK];
__device__ float g_k   [Bz*Hh*Nn*DK];
__device__ float g_v   [Bz*Hh*Nn*DK];
__device__ float g_bias[Bz*Hh*Nn*Nn];     // geo bias (read-only after K2)
__device__ float g_attn[Bz*Nn*Dm];

__device__ __forceinline__ float to_tf32(float x) {
    uint32_t u;
    asm("cvt.rna.tf32.f32 %0, %1;" : "=r"(u) : "f"(x));
    return __uint_as_float(u);
}

__device__ __forceinline__ void mma_tf32(float c[4],
                                         uint32_t a0, uint32_t a1, uint32_t a2, uint32_t a3,
                                         uint32_t b0, uint32_t b1) {
    asm volatile(
        "mma.sync.aligned.m16n8k8.row.col.f32.tf32.tf32.f32 "
        "{%0,%1,%2,%3}, {%4,%5,%6,%7}, {%8,%9}, {%0,%1,%2,%3};\n"
        : "+f"(c[0]), "+f"(c[1]), "+f"(c[2]), "+f"(c[3])
        : "r"(a0), "r"(a1), "r"(a2), "r"(a3), "r"(b0), "r"(b1));
}

__device__ __forceinline__ float4 tf32_4(float4 v) {
    v.x = to_tf32(v.x); v.y = to_tf32(v.y);
    v.z = to_tf32(v.z); v.w = to_tf32(v.w);
    return v;
}

// ---------------------------------------------------------------------------
// tf32 GEMM: C[M,512] = A[M,512] @ W[512,512] + bias
// Block tile 64x64, k-chunk 32, double-buffered smem, 128 threads.
// ---------------------------------------------------------------------------
template <bool PERM>
__device__ __forceinline__ void gemm_tf32_body(const float* __restrict__ A,
                                               const float* __restrict__ W,
                                               const float* __restrict__ bias,
                                               float* __restrict__ C)
{
    __shared__ float As[2][64][36];
    __shared__ float Bs[2][32][72];

    const int t    = threadIdx.x;
    const int lane = t & 31;
    const int w    = t >> 5;
    const int g    = lane >> 2;
    const int tig  = lane & 3;
    const int wm   = w >> 1;
    const int wn   = w & 1;
    const int rowBase = blockIdx.y * 64;
    const int colBase = blockIdx.x * 64;

    const int ar = t >> 1,  ak = (t & 1) * 16;
    const int bk = t >> 2,  bn = (t & 3) * 16;
    const float* Ap = A + (size_t)(rowBase + ar) * Dm + ak;
    const float* Wp = W + (size_t)bk * Dm + colBase + bn;

    float acc[2][4][4];
#pragma unroll
    for (int mt = 0; mt < 2; ++mt)
#pragma unroll
        for (int nt = 0; nt < 4; ++nt)
#pragma unroll
            for (int i = 0; i < 4; ++i) acc[mt][nt][i] = 0.0f;

#pragma unroll
    for (int i = 0; i < 4; ++i)
        *(float4*)&As[0][ar][ak + i * 4] = tf32_4(*(const float4*)(Ap + i * 4));
#pragma unroll
    for (int i = 0; i < 4; ++i)
        *(float4*)&Bs[0][bk][bn + i * 4] = tf32_4(*(const float4*)(Wp + i * 4));
    __syncthreads();

    const int NK = Dm / 32;
    for (int it = 0; it < NK; ++it) {
        float4 pa[4], pb[4];
        const bool more = (it + 1 < NK);
        if (more) {
            const int k0 = (it + 1) * 32;
#pragma unroll
            for (int i = 0; i < 4; ++i) pa[i] = *(const float4*)(Ap + k0 + i * 4);
#pragma unroll
            for (int i = 0; i < 4; ++i) pb[i] = *(const float4*)(Wp + (size_t)k0 * Dm + i * 4);
        }

        const int buf = it & 1;
#pragma unroll
        for (int ks = 0; ks < 32; ks += 8) {
            uint32_t afr[2][4];
#pragma unroll
            for (int mt = 0; mt < 2; ++mt) {
                int mr = wm * 32 + mt * 16 + g;
                afr[mt][0] = __float_as_uint(As[buf][mr    ][ks + tig    ]);
                afr[mt][1] = __float_as_uint(As[buf][mr + 8][ks + tig    ]);
                afr[mt][2] = __float_as_uint(As[buf][mr    ][ks + tig + 4]);
                afr[mt][3] = __float_as_uint(As[buf][mr + 8][ks + tig + 4]);
            }
            uint32_t bfr[4][2];
#pragma unroll
            for (int nt = 0; nt < 4; ++nt) {
                int nc = wn * 32 + nt * 8 + g;
                bfr[nt][0] = __float_as_uint(Bs[buf][ks + tig    ][nc]);
                bfr[nt][1] = __float_as_uint(Bs[buf][ks + tig + 4][nc]);
            }
#pragma unroll
            for (int mt = 0; mt < 2; ++mt)
#pragma unroll
                for (int nt = 0; nt < 4; ++nt)
                    mma_tf32(acc[mt][nt],
                             afr[mt][0], afr[mt][1], afr[mt][2], afr[mt][3],
                             bfr[nt][0], bfr[nt][1]);
        }

        if (more) {
            const int nb = 1 - buf;
#pragma unroll
            for (int i = 0; i < 4; ++i) *(float4*)&As[nb][ar][ak + i * 4] = tf32_4(pa[i]);
#pragma unroll
            for (int i = 0; i < 4; ++i) *(float4*)&Bs[nb][bk][bn + i * 4] = tf32_4(pb[i]);
        }
        __syncthreads();
    }

#pragma unroll
    for (int mt = 0; mt < 2; ++mt) {
#pragma unroll
        for (int nt = 0; nt < 4; ++nt) {
            int r0 = rowBase + wm * 32 + mt * 16 + g;
            int c0 = colBase + wn * 32 + nt * 8 + 2 * tig;
            float v00 = acc[mt][nt][0] + bias[c0];
            float v01 = acc[mt][nt][1] + bias[c0 + 1];
            float v10 = acc[mt][nt][2] + bias[c0];
            float v11 = acc[mt][nt][3] + bias[c0 + 1];
            if (PERM) {
                int b_ = r0 >> 8, n_ = r0 & 255, h_ = c0 >> 6, d_ = c0 & 63;
                float* p0 = C + ((((b_ * Hh + h_) * Nn) + n_) * DK + d_);
                p0[0] = v00; p0[1] = v01;
                int r1 = r0 + 8;
                int b1_ = r1 >> 8, n1_ = r1 & 255;
                float* p1 = C + ((((b1_ * Hh + h_) * Nn) + n1_) * DK + d_);
                p1[0] = v10; p1[1] = v11;
            } else {
                *(float2*)(C + (size_t)r0 * Dm + c0)       = make_float2(v00, v01);
                *(float2*)(C + (size_t)(r0 + 8) * Dm + c0) = make_float2(v10, v11);
            }
        }
    }
}

__global__ __launch_bounds__(128)
void qkv_tf32(const float* __restrict__ xq, const float* __restrict__ xk,
              const float* __restrict__ xv,
              const float* __restrict__ Wq, const float* __restrict__ bq,
              const float* __restrict__ Wk, const float* __restrict__ bk,
              const float* __restrict__ Wv, const float* __restrict__ bv)
{
    const float* A; const float* W; const float* bias; float* C;
    if (blockIdx.z == 0)      { A = xq; W = Wq; bias = bq; C = g_q; }
    else if (blockIdx.z == 1) { A = xk; W = Wk; bias = bk; C = g_k; }
    else                      { A = xv; W = Wv; bias = bv; C = g_v; }
    gemm_tf32_body<true>(A, W, bias, C);
}

__global__ __launch_bounds__(128)
void outproj_tf32(const float* __restrict__ Wo, const float* __restrict__ bo,
                  float* __restrict__ out)
{
    gemm_tf32_body<false>(g_attn, Wo, bo, out);
}

// ---------------------------------------------------------------------------
// K2: geometric bias.  One block per (b,n), one thread per m.
// ---------------------------------------------------------------------------
__global__ void geo_bias_kernel(const float* __restrict__ box,
                                const int*   __restrict__ mask,
                                const float* __restrict__ WGw,
                                const float* __restrict__ WGb)
{
    __shared__ float Ws[8][32];
    __shared__ float Wc[8][32];
    __shared__ float Wb[8];

    const int t = threadIdx.x;
    const int n = blockIdx.x;
    const int b = blockIdx.y;

    for (int idx = t; idx < Hh * 64; idx += 256) {
        int h = idx >> 6, j = idx & 63;
        float w = WGw[idx];
        if (j < 32) Ws[h][j] = w; else Wc[h][j - 32] = w;
    }
    if (t < 8) Wb[t] = WGb[t];
    __syncthreads();

    float4 bn = *(const float4*)(box + (b * Nn + n) * 4);
    float4 bm = *(const float4*)(box + (b * Nn + t) * 4);
    float cx1 = (bn.x + bn.z) * 0.5f, cy1 = (bn.y + bn.w) * 0.5f;
    float w1  = bn.z - bn.x + 1.0f,   h1  = bn.w - bn.y + 1.0f;
    float cx2 = (bm.x + bm.z) * 0.5f, cy2 = (bm.y + bm.w) * 0.5f;
    float w2  = bm.z - bm.x + 1.0f,   h2  = bm.w - bm.y + 1.0f;

    float pos[4];
    pos[0] = logf(fmaxf(fabsf((cx1 - cx2) / w1), 0.001f));
    pos[1] = logf(fmaxf(fabsf((cy1 - cy2) / h1), 0.001f));
    pos[2] = logf(w1 / w2);
    pos[3] = logf(h1 / h2);

    const float dimv[8] = {1.0f, 0.42169650342f, 0.17782794100f, 0.07498942093f,
                           0.03162277660f, 0.01333521432f, 0.00562341325f,
                           0.00237137371f};

    float acc[8];
#pragma unroll
    for (int h = 0; h < 8; ++h) acc[h] = Wb[h];

#pragma unroll
    for (int p = 0; p < 4; ++p) {
        float base = 100.0f * pos[p];
#pragma unroll
        for (int f = 0; f < 8; ++f) {
            float s, c;
            sincosf(base * dimv[f], &s, &c);
            int j = p * 8 + f;
#pragma unroll
            for (int h = 0; h < 8; ++h) {
                acc[h] = fmaf(s, Ws[h][j], acc[h]);
                acc[h] = fmaf(c, Wc[h][j], acc[h]);
            }
        }
    }

    float mterm = (mask[b * Nn + t] == 0) ? -1e9f : 0.0f;
#pragma unroll
    for (int h = 0; h < 8; ++h) {
        float val = logf(fmaxf(acc[h], 1e-6f)) + mterm;
        g_bias[(((b * Hh + h) * Nn) + n) * Nn + t] = val;
    }
}

// ---------------------------------------------------------------------------
// K3: fused attention core.  Block = 32 q-rows x all 256 keys of one (b,h).
// 256 threads / 8 warps.
//   Phase S : warps (wr 0..1 rows, wc 0..3) compute S in regs via tf32 mma,
//             K staged in 64-key chunks.  S += bias (read once), /8.
//   Softmax : exact, in registers (quad shuffles + smem cross-warp reduce).
//   Phase PV: normalized P -> smem, V staged in 32-key chunks, tf32 mma.
// smem: union( Qs[32][68]+Ks[64][68] , Ps[32][260]+Vs[32][68] ) = 42KB.
// ---------------------------------------------------------------------------
#define QS(r,c)  sm_f[(r) * 68 + (c)]
#define KS(r,c)  sm_f[2176 + (r) * 68 + (c)]
#define PS(r,c)  sm_f[(r) * 260 + (c)]
#define VS(r,c)  sm_f[8320 + (r) * 68 + (c)]

__global__ __launch_bounds__(256)
void attn_core_kernel()
{
    __shared__ __align__(16) float sm_f[10496];     // 42KB union
    __shared__ float redmax[32][4];
    __shared__ float redsum[32][4];

    const int z = blockIdx.y;                 // b*8+h
    const int b = z >> 3, h = z & 7;
    const int rowBase = blockIdx.x * 32;
    const float* Q  = g_q + (size_t)z * (Nn * DK);
    const float* Kg = g_k + (size_t)z * (Nn * DK);
    const float* Vg = g_v + (size_t)z * (Nn * DK);
    const float* Bias = g_bias + (size_t)z * (Nn * Nn);

    const int t    = threadIdx.x;
    const int lane = t & 31;
    const int w    = t >> 5;
    const int g    = lane >> 2;
    const int tig  = lane & 3;
    const int wr   = w >> 2;          // 0..1 : 16-row group
    const int wc   = w & 3;           // 0..3 : 16-col group within 64-key chunk
    const int rl   = wr * 16 + g;     // local rows rl, rl+8

    // stage Q (32x64): 256 thr x 8 floats
    {
        const int qr = t >> 3, qc = (t & 7) * 8;
        *(float4*)&QS(qr, qc)     = tf32_4(*(const float4*)(Q + (size_t)(rowBase + qr) * DK + qc));
        *(float4*)&QS(qr, qc + 4) = tf32_4(*(const float4*)(Q + (size_t)(rowBase + qr) * DK + qc + 4));
    }

    float s[4][2][4];                 // [key chunk][nt][frag]
#pragma unroll
    for (int cc = 0; cc < 4; ++cc)
#pragma unroll
        for (int nt = 0; nt < 2; ++nt)
#pragma unroll
            for (int i = 0; i < 4; ++i) s[cc][nt][i] = 0.0f;

    // ---- S = Q K^T, K in 64-key chunks ----
    const int kr = t >> 2, kc = (t & 3) * 16;
    for (int cc = 0; cc < 4; ++cc) {
        __syncthreads();
#pragma unroll
        for (int i = 0; i < 4; ++i)
            *(float4*)&KS(kr, kc + i * 4) =
                tf32_4(*(const float4*)(Kg + (size_t)(cc * 64 + kr) * DK + kc + i * 4));
        __syncthreads();

#pragma unroll
        for (int ks = 0; ks < 64; ks += 8) {
            uint32_t a0 = __float_as_uint(QS(rl    , ks + tig    ));
            uint32_t a1 = __float_as_uint(QS(rl + 8, ks + tig    ));
            uint32_t a2 = __float_as_uint(QS(rl    , ks + tig + 4));
            uint32_t a3 = __float_as_uint(QS(rl + 8, ks + tig + 4));
#pragma unroll
            for (int nt = 0; nt < 2; ++nt) {
                int nc = wc * 16 + nt * 8 + g;
                uint32_t b0 = __float_as_uint(KS(nc, ks + tig    ));
                uint32_t b1 = __float_as_uint(KS(nc, ks + tig + 4));
                mma_tf32(s[cc][nt], a0, a1, a2, a3, b0, b1);
            }
        }
    }

    // ---- scale + bias ----
#pragma unroll
    for (int cc = 0; cc < 4; ++cc)
#pragma unroll
        for (int nt = 0; nt < 2; ++nt) {
            int col = cc * 64 + wc * 16 + nt * 8 + 2 * tig;
            float2 b0v = *(const float2*)(Bias + (size_t)(rowBase + rl) * Nn + col);
            float2 b1v = *(const float2*)(Bias + (size_t)(rowBase + rl + 8) * Nn + col);
            s[cc][nt][0] = fmaf(s[cc][nt][0], 0.125f, b0v.x);
            s[cc][nt][1] = fmaf(s[cc][nt][1], 0.125f, b0v.y);
            s[cc][nt][2] = fmaf(s[cc][nt][2], 0.125f, b1v.x);
            s[cc][nt][3] = fmaf(s[cc][nt][3], 0.125f, b1v.y);
        }

    // ---- exact softmax over 256 cols ----
    float m0 = -1e30f, m1 = -1e30f;
#pragma unroll
    for (int cc = 0; cc < 4; ++cc)
#pragma unroll
        for (int nt = 0; nt < 2; ++nt) {
            m0 = fmaxf(m0, fmaxf(s[cc][nt][0], s[cc][nt][1]));
            m1 = fmaxf(m1, fmaxf(s[cc][nt][2], s[cc][nt][3]));
        }
    m0 = fmaxf(m0, __shfl_xor_sync(0xffffffffu, m0, 1));
    m0 = fmaxf(m0, __shfl_xor_sync(0xffffffffu, m0, 2));
    m1 = fmaxf(m1, __shfl_xor_sync(0xffffffffu, m1, 1));
    m1 = fmaxf(m1, __shfl_xor_sync(0xffffffffu, m1, 2));
    if (tig == 0) { redmax[rl][wc] = m0; redmax[rl + 8][wc] = m1; }
    __syncthreads();
    m0 = fmaxf(fmaxf(redmax[rl][0], redmax[rl][1]),
               fmaxf(redmax[rl][2], redmax[rl][3]));
    m1 = fmaxf(fmaxf(redmax[rl + 8][0], redmax[rl + 8][1]),
               fmaxf(redmax[rl + 8][2], redmax[rl + 8][3]));

    float l0 = 0.0f, l1 = 0.0f;
#pragma unroll
    for (int cc = 0; cc < 4; ++cc)
#pragma unroll
        for (int nt = 0; nt < 2; ++nt) {
            s[cc][nt][0] = __expf(s[cc][nt][0] - m0);
            s[cc][nt][1] = __expf(s[cc][nt][1] - m0);
            s[cc][nt][2] = __expf(s[cc][nt][2] - m1);
            s[cc][nt][3] = __expf(s[cc][nt][3] - m1);
            l0 += s[cc][nt][0] + s[cc][nt][1];
            l1 += s[cc][nt][2] + s[cc][nt][3];
        }
    l0 += __shfl_xor_sync(0xffffffffu, l0, 1);
    l0 += __shfl_xor_sync(0xffffffffu, l0, 2);
    l1 += __shfl_xor_sync(0xffffffffu, l1, 1);
    l1 += __shfl_xor_sync(0xffffffffu, l1, 2);
    if (tig == 0) { redsum[rl][wc] = l0; redsum[rl + 8][wc] = l1; }
    __syncthreads();
    l0 = redsum[rl][0] + redsum[rl][1] + redsum[rl][2] + redsum[rl][3];
    l1 = redsum[rl + 8][0] + redsum[rl + 8][1] + redsum[rl + 8][2] + redsum[rl + 8][3];
    const float inv0 = __frcp_rn(l0);
    const float inv1 = __frcp_rn(l1);

    // ---- write normalized P to smem (overwrites Q/K staging) ----
    __syncthreads();
#pragma unroll
    for (int cc = 0; cc < 4; ++cc)
#pragma unroll
        for (int nt = 0; nt < 2; ++nt) {
            int col = cc * 64 + wc * 16 + nt * 8 + 2 * tig;
            PS(rl,     col)     = to_tf32(s[cc][nt][0] * inv0);
            PS(rl,     col + 1) = to_tf32(s[cc][nt][1] * inv0);
            PS(rl + 8, col)     = to_tf32(s[cc][nt][2] * inv1);
            PS(rl + 8, col + 1) = to_tf32(s[cc][nt][3] * inv1);
        }

    // ---- O = P @ V, V staged in 32-key chunks ----
    const int wn = w & 3;             // 16 output dims per warp
    float o[2][4];
#pragma unroll
    for (int nt = 0; nt < 2; ++nt)
#pragma unroll
        for (int i = 0; i < 4; ++i) o[nt][i] = 0.0f;

    const int vr = t >> 3, vc = (t & 7) * 8;
    for (int kc2 = 0; kc2 < 8; ++kc2) {
        __syncthreads();
        *(float4*)&VS(vr, vc)     = tf32_4(*(const float4*)(Vg + (size_t)(kc2 * 32 + vr) * DK + vc));
        *(float4*)&VS(vr, vc + 4) = tf32_4(*(const float4*)(Vg + (size_t)(kc2 * 32 + vr) * DK + vc + 4));
        __syncthreads();

#pragma unroll
        for (int ks = 0; ks < 32; ks += 8) {
            uint32_t a0 = __float_as_uint(PS(rl    , kc2 * 32 + ks + tig    ));
            uint32_t a1 = __float_as_uint(PS(rl + 8, kc2 * 32 + ks + tig    ));
            uint32_t a2 = __float_as_uint(PS(rl    , kc2 * 32 + ks + tig + 4));
            uint32_t a3 = __float_as_uint(PS(rl + 8, kc2 * 32 + ks + tig + 4));
#pragma unroll
            for (int nt = 0; nt < 2; ++nt) {
                int nc = wn * 16 + nt * 8 + g;
                uint32_t b0 = __float_as_uint(VS(ks + tig    , nc));
                uint32_t b1 = __float_as_uint(VS(ks + tig + 4, nc));
                mma_tf32(o[nt], a0, a1, a2, a3, b0, b1);
            }
        }
    }

    // ---- write O: [B, N, H*64] ----
#pragma unroll
    for (int nt = 0; nt < 2; ++nt) {
        int d = wn * 16 + nt * 8 + 2 * tig;
        float* p0 = g_attn + ((size_t)(b * Nn + rowBase + rl) * Dm + h * DK + d);
        float* p1 = g_attn + ((size_t)(b * Nn + rowBase + rl + 8) * Dm + h * DK + d);
        *(float2*)p0 = make_float2(o[nt][0], o[nt][1]);
        *(float2*)p1 = make_float2(o[nt][2], o[nt][3]);
    }
}

// ---------------------------------------------------------------------------
extern "C" void kernel_launch(void* const* d_in, const int* in_sizes, int n_in,
                              void* d_out, int out_size)
{
    const float* xq  = (const float*)d_in[0];
    const float* xk  = (const float*)d_in[1];
    const float* xv  = (const float*)d_in[2];
    const float* box = (const float*)d_in[3];
    const int*   msk = (const int*)  d_in[4];
    const float* Wq  = (const float*)d_in[5];
    const float* bq  = (const float*)d_in[6];
    const float* Wk  = (const float*)d_in[7];
    const float* bk  = (const float*)d_in[8];
    const float* Wv  = (const float*)d_in[9];
    const float* bv  = (const float*)d_in[10];
    const float* Wo  = (const float*)d_in[11];
    const float* bo  = (const float*)d_in[12];
    const float* WGw = (const float*)d_in[13];
    const float* WGb = (const float*)d_in[14];
    float* out = (float*)d_out;

    qkv_tf32<<<dim3(8, 64, 3), 128>>>(xq, xk, xv, Wq, bq, Wk, bk, Wv, bv);
    geo_bias_kernel<<<dim3(Nn, Bz), 256>>>(box, msk, WGw, WGb);
    attn_core_kernel<<<dim3(8, Bz * Hh), 256>>>();
    outproj_tf32<<<dim3(8, 64, 1), 128>>>(Wo, bo, out);
}

// round 9
// speedup vs baseline: 1.5340x; 1.1088x over previous
#include <cuda_runtime.h>
#include <cuda_bf16.h>
#include <cstdint>

// ---------------------------------------------------------------------------
// BoxMultiHeadedAttention  (B=16, N=256, D=512, H=8, d_k=64, dim_g=64)
//
//  K1 fused_qkv_geo : blocks 0..1535  -> q,k,v = (X@W+b) [tf32 mma 64x64/256t]
//                     blocks 1536..   -> geo bias (runs CONCURRENTLY)
//  K2 attn_core     : O = softmax(bias + qk^T/8) @ V  (fused, tf32 mma)
//  K3 outproj       : out = attn @ Wo + bo
// ---------------------------------------------------------------------------

#define Bz   16
#define Nn   256
#define Dm   512
#define Hh   8
#define DK   64

__device__ float g_q   [Bz*Hh*Nn*DK];
__device__ float g_k   [Bz*Hh*Nn*DK];
__device__ float g_v   [Bz*Hh*Nn*DK];
__device__ float g_bias[Bz*Hh*Nn*Nn];     // geo bias (read-only after K1)
__device__ float g_attn[Bz*Nn*Dm];

__device__ __forceinline__ float to_tf32(float x) {
    uint32_t u;
    asm("cvt.rna.tf32.f32 %0, %1;" : "=r"(u) : "f"(x));
    return __uint_as_float(u);
}

__device__ __forceinline__ void mma_tf32(float c[4],
                                         uint32_t a0, uint32_t a1, uint32_t a2, uint32_t a3,
                                         uint32_t b0, uint32_t b1) {
    asm volatile(
        "mma.sync.aligned.m16n8k8.row.col.f32.tf32.tf32.f32 "
        "{%0,%1,%2,%3}, {%4,%5,%6,%7}, {%8,%9}, {%0,%1,%2,%3};\n"
        : "+f"(c[0]), "+f"(c[1]), "+f"(c[2]), "+f"(c[3])
        : "r"(a0), "r"(a1), "r"(a2), "r"(a3), "r"(b0), "r"(b1));
}

__device__ __forceinline__ float4 tf32_4(float4 v) {
    v.x = to_tf32(v.x); v.y = to_tf32(v.y);
    v.z = to_tf32(v.z); v.w = to_tf32(v.w);
    return v;
}

// ---------------------------------------------------------------------------
// tf32 GEMM body: C[64x64 tile] = A[.,512] @ W[512,512] + bias
// 256 threads / 8 warps, warp tile 32x16, k-chunk 32, double-buffered.
// ---------------------------------------------------------------------------
template <bool PERM>
__device__ __forceinline__ void gemm_tf32_body(const float* __restrict__ A,
                                               const float* __restrict__ W,
                                               const float* __restrict__ bias,
                                               float* __restrict__ C,
                                               int rowBase, int colBase)
{
    __shared__ float As[2][64][36];
    __shared__ float Bs[2][32][72];

    const int t    = threadIdx.x;
    const int lane = t & 31;
    const int w    = t >> 5;
    const int g    = lane >> 2;
    const int tig  = lane & 3;
    const int wm   = w >> 2;          // 0..1
    const int wn   = w & 3;           // 0..3

    const int ar = t >> 2,  ak = (t & 3) * 8;   // A: 64 rows x 32 k, 8/thread
    const int bk = t >> 3,  bn = (t & 7) * 8;   // B: 32 k x 64 n, 8/thread
    const float* Ap = A + (size_t)(rowBase + ar) * Dm + ak;
    const float* Wp = W + (size_t)bk * Dm + colBase + bn;

    float acc[2][2][4];
#pragma unroll
    for (int mt = 0; mt < 2; ++mt)
#pragma unroll
        for (int nt = 0; nt < 2; ++nt)
#pragma unroll
            for (int i = 0; i < 4; ++i) acc[mt][nt][i] = 0.0f;

    // prologue: chunk 0 -> buf 0
    *(float4*)&As[0][ar][ak]     = tf32_4(*(const float4*)(Ap));
    *(float4*)&As[0][ar][ak + 4] = tf32_4(*(const float4*)(Ap + 4));
    *(float4*)&Bs[0][bk][bn]     = tf32_4(*(const float4*)(Wp));
    *(float4*)&Bs[0][bk][bn + 4] = tf32_4(*(const float4*)(Wp + 4));
    __syncthreads();

    const int NK = Dm / 32;          // 16
    for (int it = 0; it < NK; ++it) {
        float4 pa0, pa1, pb0, pb1;
        const bool more = (it + 1 < NK);
        if (more) {
            const int k0 = (it + 1) * 32;
            pa0 = *(const float4*)(Ap + k0);
            pa1 = *(const float4*)(Ap + k0 + 4);
            pb0 = *(const float4*)(Wp + (size_t)k0 * Dm);
            pb1 = *(const float4*)(Wp + (size_t)k0 * Dm + 4);
        }

        const int buf = it & 1;
#pragma unroll
        for (int ks = 0; ks < 32; ks += 8) {
            uint32_t afr[2][4];
#pragma unroll
            for (int mt = 0; mt < 2; ++mt) {
                int mr = wm * 32 + mt * 16 + g;
                afr[mt][0] = __float_as_uint(As[buf][mr    ][ks + tig    ]);
                afr[mt][1] = __float_as_uint(As[buf][mr + 8][ks + tig    ]);
                afr[mt][2] = __float_as_uint(As[buf][mr    ][ks + tig + 4]);
                afr[mt][3] = __float_as_uint(As[buf][mr + 8][ks + tig + 4]);
            }
            uint32_t bfr[2][2];
#pragma unroll
            for (int nt = 0; nt < 2; ++nt) {
                int nc = wn * 16 + nt * 8 + g;
                bfr[nt][0] = __float_as_uint(Bs[buf][ks + tig    ][nc]);
                bfr[nt][1] = __float_as_uint(Bs[buf][ks + tig + 4][nc]);
            }
#pragma unroll
            for (int mt = 0; mt < 2; ++mt)
#pragma unroll
                for (int nt = 0; nt < 2; ++nt)
                    mma_tf32(acc[mt][nt],
                             afr[mt][0], afr[mt][1], afr[mt][2], afr[mt][3],
                             bfr[nt][0], bfr[nt][1]);
        }

        if (more) {
            const int nb = 1 - buf;
            *(float4*)&As[nb][ar][ak]     = tf32_4(pa0);
            *(float4*)&As[nb][ar][ak + 4] = tf32_4(pa1);
            *(float4*)&Bs[nb][bk][bn]     = tf32_4(pb0);
            *(float4*)&Bs[nb][bk][bn + 4] = tf32_4(pb1);
        }
        __syncthreads();
    }

#pragma unroll
    for (int mt = 0; mt < 2; ++mt) {
#pragma unroll
        for (int nt = 0; nt < 2; ++nt) {
            int r0 = rowBase + wm * 32 + mt * 16 + g;
            int c0 = colBase + wn * 16 + nt * 8 + 2 * tig;
            float v00 = acc[mt][nt][0] + bias[c0];
            float v01 = acc[mt][nt][1] + bias[c0 + 1];
            float v10 = acc[mt][nt][2] + bias[c0];
            float v11 = acc[mt][nt][3] + bias[c0 + 1];
            if (PERM) {
                int b_ = r0 >> 8, n_ = r0 & 255, h_ = c0 >> 6, d_ = c0 & 63;
                float* p0 = C + ((((b_ * Hh + h_) * Nn) + n_) * DK + d_);
                p0[0] = v00; p0[1] = v01;
                int r1 = r0 + 8;
                int b1_ = r1 >> 8, n1_ = r1 & 255;
                float* p1 = C + ((((b1_ * Hh + h_) * Nn) + n1_) * DK + d_);
                p1[0] = v10; p1[1] = v11;
            } else {
                *(float2*)(C + (size_t)r0 * Dm + c0)       = make_float2(v00, v01);
                *(float2*)(C + (size_t)(r0 + 8) * Dm + c0) = make_float2(v10, v11);
            }
        }
    }
}

// ---------------------------------------------------------------------------
// geo-bias body: one block per (b,n), one thread per m (256 threads).
// ---------------------------------------------------------------------------
__device__ __forceinline__ void geo_body(const float* __restrict__ box,
                                         const int*   __restrict__ mask,
                                         const float* __restrict__ WGw,
                                         const float* __restrict__ WGb,
                                         int b, int n)
{
    __shared__ float Ws[8][32];
    __shared__ float Wc[8][32];
    __shared__ float Wb[8];

    const int t = threadIdx.x;      // m

    for (int idx = t; idx < Hh * 64; idx += 256) {
        int h = idx >> 6, j = idx & 63;
        float w = WGw[idx];
        if (j < 32) Ws[h][j] = w; else Wc[h][j - 32] = w;
    }
    if (t < 8) Wb[t] = WGb[t];
    __syncthreads();

    float4 bn = *(const float4*)(box + (b * Nn + n) * 4);
    float4 bm = *(const float4*)(box + (b * Nn + t) * 4);
    float cx1 = (bn.x + bn.z) * 0.5f, cy1 = (bn.y + bn.w) * 0.5f;
    float w1  = bn.z - bn.x + 1.0f,   h1  = bn.w - bn.y + 1.0f;
    float cx2 = (bm.x + bm.z) * 0.5f, cy2 = (bm.y + bm.w) * 0.5f;
    float w2  = bm.z - bm.x + 1.0f,   h2  = bm.w - bm.y + 1.0f;

    float pos[4];
    pos[0] = logf(fmaxf(fabsf((cx1 - cx2) / w1), 0.001f));
    pos[1] = logf(fmaxf(fabsf((cy1 - cy2) / h1), 0.001f));
    pos[2] = logf(w1 / w2);
    pos[3] = logf(h1 / h2);

    const float dimv[8] = {1.0f, 0.42169650342f, 0.17782794100f, 0.07498942093f,
                           0.03162277660f, 0.01333521432f, 0.00562341325f,
                           0.00237137371f};

    float acc[8];
#pragma unroll
    for (int h = 0; h < 8; ++h) acc[h] = Wb[h];

#pragma unroll
    for (int p = 0; p < 4; ++p) {
        float base = 100.0f * pos[p];
#pragma unroll
        for (int f = 0; f < 8; ++f) {
            float s, c;
            sincosf(base * dimv[f], &s, &c);
            int j = p * 8 + f;
#pragma unroll
            for (int h = 0; h < 8; ++h) {
                acc[h] = fmaf(s, Ws[h][j], acc[h]);
                acc[h] = fmaf(c, Wc[h][j], acc[h]);
            }
        }
    }

    float mterm = (mask[b * Nn + t] == 0) ? -1e9f : 0.0f;
#pragma unroll
    for (int h = 0; h < 8; ++h) {
        float val = logf(fmaxf(acc[h], 1e-6f)) + mterm;
        g_bias[(((b * Hh + h) * Nn) + n) * Nn + t] = val;
    }
}

// ---------------------------------------------------------------------------
// K1: fat kernel.  Blocks [0,1536) = qkv GEMM tiles; [1536, 5632) = geo bias.
// The two groups are independent and fill the machine together.
// ---------------------------------------------------------------------------
__global__ __launch_bounds__(256)
void fused_qkv_geo(const float* __restrict__ xq, const float* __restrict__ xk,
                   const float* __restrict__ xv,
                   const float* __restrict__ Wq, const float* __restrict__ bq,
                   const float* __restrict__ Wk, const float* __restrict__ bk,
                   const float* __restrict__ Wv, const float* __restrict__ bv,
                   const float* __restrict__ box, const int* __restrict__ msk,
                   const float* __restrict__ WGw, const float* __restrict__ WGb)
{
    const int i = blockIdx.x;
    if (i < 1536) {
        const int bx = i & 7;            // 8 col tiles (N=512)
        const int by = (i >> 3) & 63;    // 64 row tiles (M=4096)
        const int z  = i >> 9;           // 0,1,2 -> q,k,v
        const float* A; const float* W; const float* bias; float* C;
        if (z == 0)      { A = xq; W = Wq; bias = bq; C = g_q; }
        else if (z == 1) { A = xk; W = Wk; bias = bk; C = g_k; }
        else             { A = xv; W = Wv; bias = bv; C = g_v; }
        gemm_tf32_body<true>(A, W, bias, C, by * 64, bx * 64);
    } else {
        const int j = i - 1536;
        geo_body(box, msk, WGw, WGb, j >> 8, j & 255);
    }
}

__global__ __launch_bounds__(256)
void outproj_tf32(const float* __restrict__ Wo, const float* __restrict__ bo,
                  float* __restrict__ out)
{
    gemm_tf32_body<false>(g_attn, Wo, bo, out, blockIdx.y * 64, blockIdx.x * 64);
}

// ---------------------------------------------------------------------------
// K2: fused attention core.  Block = 32 q-rows x 256 keys of one (b,h).
// ---------------------------------------------------------------------------
#define QS(r,c)  sm_f[(r) * 68 + (c)]
#define KS(r,c)  sm_f[2176 + (r) * 68 + (c)]
#define PS(r,c)  sm_f[(r) * 260 + (c)]
#define VS(r,c)  sm_f[8320 + (r) * 68 + (c)]

__global__ __launch_bounds__(256)
void attn_core_kernel()
{
    __shared__ __align__(16) float sm_f[10496];     // 42KB union
    __shared__ float redmax[32][4];
    __shared__ float redsum[32][4];

    const int z = blockIdx.y;                 // b*8+h
    const int b = z >> 3, h = z & 7;
    const int rowBase = blockIdx.x * 32;
    const float* Q  = g_q + (size_t)z * (Nn * DK);
    const float* Kg = g_k + (size_t)z * (Nn * DK);
    const float* Vg = g_v + (size_t)z * (Nn * DK);
    const float* Bias = g_bias + (size_t)z * (Nn * Nn);

    const int t    = threadIdx.x;
    const int lane = t & 31;
    const int w    = t >> 5;
    const int g    = lane >> 2;
    const int tig  = lane & 3;
    const int wr   = w >> 2;
    const int wc   = w & 3;
    const int rl   = wr * 16 + g;

    {
        const int qr = t >> 3, qc = (t & 7) * 8;
        *(float4*)&QS(qr, qc)     = tf32_4(*(const float4*)(Q + (size_t)(rowBase + qr) * DK + qc));
        *(float4*)&QS(qr, qc + 4) = tf32_4(*(const float4*)(Q + (size_t)(rowBase + qr) * DK + qc + 4));
    }

    float s[4][2][4];
#pragma unroll
    for (int cc = 0; cc < 4; ++cc)
#pragma unroll
        for (int nt = 0; nt < 2; ++nt)
#pragma unroll
            for (int i = 0; i < 4; ++i) s[cc][nt][i] = 0.0f;

    const int kr = t >> 2, kc = (t & 3) * 16;
    for (int cc = 0; cc < 4; ++cc) {
        __syncthreads();
#pragma unroll
        for (int i = 0; i < 4; ++i)
            *(float4*)&KS(kr, kc + i * 4) =
                tf32_4(*(const float4*)(Kg + (size_t)(cc * 64 + kr) * DK + kc + i * 4));
        __syncthreads();

#pragma unroll
        for (int ks = 0; ks < 64; ks += 8) {
            uint32_t a0 = __float_as_uint(QS(rl    , ks + tig    ));
            uint32_t a1 = __float_as_uint(QS(rl + 8, ks + tig    ));
            uint32_t a2 = __float_as_uint(QS(rl    , ks + tig + 4));
            uint32_t a3 = __float_as_uint(QS(rl + 8, ks + tig + 4));
#pragma unroll
            for (int nt = 0; nt < 2; ++nt) {
                int nc = wc * 16 + nt * 8 + g;
                uint32_t b0 = __float_as_uint(KS(nc, ks + tig    ));
                uint32_t b1 = __float_as_uint(KS(nc, ks + tig + 4));
                mma_tf32(s[cc][nt], a0, a1, a2, a3, b0, b1);
            }
        }
    }

#pragma unroll
    for (int cc = 0; cc < 4; ++cc)
#pragma unroll
        for (int nt = 0; nt < 2; ++nt) {
            int col = cc * 64 + wc * 16 + nt * 8 + 2 * tig;
            float2 b0v = *(const float2*)(Bias + (size_t)(rowBase + rl) * Nn + col);
            float2 b1v = *(const float2*)(Bias + (size_t)(rowBase + rl + 8) * Nn + col);
            s[cc][nt][0] = fmaf(s[cc][nt][0], 0.125f, b0v.x);
            s[cc][nt][1] = fmaf(s[cc][nt][1], 0.125f, b0v.y);
            s[cc][nt][2] = fmaf(s[cc][nt][2], 0.125f, b1v.x);
            s[cc][nt][3] = fmaf(s[cc][nt][3], 0.125f, b1v.y);
        }

    float m0 = -1e30f, m1 = -1e30f;
#pragma unroll
    for (int cc = 0; cc < 4; ++cc)
#pragma unroll
        for (int nt = 0; nt < 2; ++nt) {
            m0 = fmaxf(m0, fmaxf(s[cc][nt][0], s[cc][nt][1]));
            m1 = fmaxf(m1, fmaxf(s[cc][nt][2], s[cc][nt][3]));
        }
    m0 = fmaxf(m0, __shfl_xor_sync(0xffffffffu, m0, 1));
    m0 = fmaxf(m0, __shfl_xor_sync(0xffffffffu, m0, 2));
    m1 = fmaxf(m1, __shfl_xor_sync(0xffffffffu, m1, 1));
    m1 = fmaxf(m1, __shfl_xor_sync(0xffffffffu, m1, 2));
    if (tig == 0) { redmax[rl][wc] = m0; redmax[rl + 8][wc] = m1; }
    __syncthreads();
    m0 = fmaxf(fmaxf(redmax[rl][0], redmax[rl][1]),
               fmaxf(redmax[rl][2], redmax[rl][3]));
    m1 = fmaxf(fmaxf(redmax[rl + 8][0], redmax[rl + 8][1]),
               fmaxf(redmax[rl + 8][2], redmax[rl + 8][3]));

    float l0 = 0.0f, l1 = 0.0f;
#pragma unroll
    for (int cc = 0; cc < 4; ++cc)
#pragma unroll
        for (int nt = 0; nt < 2; ++nt) {
            s[cc][nt][0] = __expf(s[cc][nt][0] - m0);
            s[cc][nt][1] = __expf(s[cc][nt][1] - m0);
            s[cc][nt][2] = __expf(s[cc][nt][2] - m1);
            s[cc][nt][3] = __expf(s[cc][nt][3] - m1);
            l0 += s[cc][nt][0] + s[cc][nt][1];
            l1 += s[cc][nt][2] + s[cc][nt][3];
        }
    l0 += __shfl_xor_sync(0xffffffffu, l0, 1);
    l0 += __shfl_xor_sync(0xffffffffu, l0, 2);
    l1 += __shfl_xor_sync(0xffffffffu, l1, 1);
    l1 += __shfl_xor_sync(0xffffffffu, l1, 2);
    if (tig == 0) { redsum[rl][wc] = l0; redsum[rl + 8][wc] = l1; }
    __syncthreads();
    l0 = redsum[rl][0] + redsum[rl][1] + redsum[rl][2] + redsum[rl][3];
    l1 = redsum[rl + 8][0] + redsum[rl + 8][1] + redsum[rl + 8][2] + redsum[rl + 8][3];
    const float inv0 = __frcp_rn(l0);
    const float inv1 = __frcp_rn(l1);

    __syncthreads();
#pragma unroll
    for (int cc = 0; cc < 4; ++cc)
#pragma unroll
        for (int nt = 0; nt < 2; ++nt) {
            int col = cc * 64 + wc * 16 + nt * 8 + 2 * tig;
            PS(rl,     col)     = to_tf32(s[cc][nt][0] * inv0);
            PS(rl,     col + 1) = to_tf32(s[cc][nt][1] * inv0);
            PS(rl + 8, col)     = to_tf32(s[cc][nt][2] * inv1);
            PS(rl + 8, col + 1) = to_tf32(s[cc][nt][3] * inv1);
        }

    const int wn = w & 3;
    float o[2][4];
#pragma unroll
    for (int nt = 0; nt < 2; ++nt)
#pragma unroll
        for (int i = 0; i < 4; ++i) o[nt][i] = 0.0f;

    const int vr = t >> 3, vc = (t & 7) * 8;
    for (int kc2 = 0; kc2 < 8; ++kc2) {
        __syncthreads();
        *(float4*)&VS(vr, vc)     = tf32_4(*(const float4*)(Vg + (size_t)(kc2 * 32 + vr) * DK + vc));
        *(float4*)&VS(vr, vc + 4) = tf32_4(*(const float4*)(Vg + (size_t)(kc2 * 32 + vr) * DK + vc + 4));
        __syncthreads();

#pragma unroll
        for (int ks = 0; ks < 32; ks += 8) {
            uint32_t a0 = __float_as_uint(PS(rl    , kc2 * 32 + ks + tig    ));
            uint32_t a1 = __float_as_uint(PS(rl + 8, kc2 * 32 + ks + tig    ));
            uint32_t a2 = __float_as_uint(PS(rl    , kc2 * 32 + ks + tig + 4));
            uint32_t a3 = __float_as_uint(PS(rl + 8, kc2 * 32 + ks + tig + 4));
#pragma unroll
            for (int nt = 0; nt < 2; ++nt) {
                int nc = wn * 16 + nt * 8 + g;
                uint32_t b0 = __float_as_uint(VS(ks + tig    , nc));
                uint32_t b1 = __float_as_uint(VS(ks + tig + 4, nc));
                mma_tf32(o[nt], a0, a1, a2, a3, b0, b1);
            }
        }
    }

#pragma unroll
    for (int nt = 0; nt < 2; ++nt) {
        int d = wn * 16 + nt * 8 + 2 * tig;
        float* p0 = g_attn + ((size_t)(b * Nn + rowBase + rl) * Dm + h * DK + d);
        float* p1 = g_attn + ((size_t)(b * Nn + rowBase + rl + 8) * Dm + h * DK + d);
        *(float2*)p0 = make_float2(o[nt][0], o[nt][1]);
        *(float2*)p1 = make_float2(o[nt][2], o[nt][3]);
    }
}

// ---------------------------------------------------------------------------
extern "C" void kernel_launch(void* const* d_in, const int* in_sizes, int n_in,
                              void* d_out, int out_size)
{
    const float* xq  = (const float*)d_in[0];
    const float* xk  = (const float*)d_in[1];
    const float* xv  = (const float*)d_in[2];
    const float* box = (const float*)d_in[3];
    const int*   msk = (const int*)  d_in[4];
    const float* Wq  = (const float*)d_in[5];
    const float* bq  = (const float*)d_in[6];
    const float* Wk  = (const float*)d_in[7];
    const float* bk  = (const float*)d_in[8];
    const float* Wv  = (const float*)d_in[9];
    const float* bv  = (const float*)d_in[10];
    const float* Wo  = (const float*)d_in[11];
    const float* bo  = (const float*)d_in[12];
    const float* WGw = (const float*)d_in[13];
    const float* WGb = (const float*)d_in[14];
    float* out = (float*)d_out;

    fused_qkv_geo<<<1536 + Bz * Nn, 256>>>(xq, xk, xv, Wq, bq, Wk, bk, Wv, bv,
                                           box, msk, WGw, WGb);
    attn_core_kernel<<<dim3(8, Bz * Hh), 256>>>();
    outproj_tf32<<<dim3(8, 64), 256>>>(Wo, bo, out);
}